// round 14
// baseline (speedup 1.0000x reference)
#include <cuda_runtime.h>
#include <cuda_bf16.h>
#include <math.h>
#include <stdint.h>

#define VOCAB 50257
#define DMEAN 1024
#define DMV   1024
#define BATCH 32
#define SEQL  128
#define TOTW  ((size_t)DMV * VOCAB)       // W1 total words

// ---- k2 tf32 pipeline config ----
#define TM      256                       // vocab cols per block -> 1KB strips
#define KSTG    16                        // k rows per stage
#define NSTG    (DMV / KSTG)              // 64
#define DEPTH   3
#define AST     260                       // 65 granules: covers (k&3)+256 <= 259
#define BST     20                        // 20 % 32: mq*20 distinct mod 32 -> conflict-free B
#define AW_STG  (KSTG * AST)              // 4160 words
#define BW_STG  (BATCH * BST)             // 640 words
#define K2_SMEM ((DEPTH * (AW_STG + BW_STG)) * 4)   // 57600 B
#define NBV     ((VOCAB + TM - 1) / TM)   // 197

// Scratch (device globals — no runtime allocation allowed)
__device__ float g_h[BATCH * DMV];
__device__ float g_logits[BATCH * VOCAB];
__device__ float g_red[BATCH][NBV][2];    // per (row, block) {max, sumexp}

// ---------------------------------------------------------------------------
#define MMA1688(c, a, bb0, bb1)                                                \
    asm volatile("mma.sync.aligned.m16n8k8.row.col.f32.tf32.tf32.f32 "         \
                 "{%0,%1,%2,%3}, {%4,%5,%6,%7}, {%8,%9}, {%0,%1,%2,%3};"       \
                 : "+f"(c[0]), "+f"(c[1]), "+f"(c[2]), "+f"(c[3])              \
                 : "r"(a[0]), "r"(a[1]), "r"(a[2]), "r"(a[3]),                 \
                   "r"(bb0), "r"(bb1))

__device__ __forceinline__ void cp_async16(uint32_t dst, const void* src) {
    asm volatile("cp.async.cg.shared.global [%0], [%1], 16;"
                 :: "r"(dst), "l"(src) : "memory");
}
__device__ __forceinline__ uint32_t lds32(uint32_t a) {
    uint32_t v;
    asm volatile("ld.shared.b32 %0, [%1];" : "=r"(v) : "r"(a));
    return v;
}
#define CP_COMMIT() asm volatile("cp.async.commit_group;" ::: "memory")
#define CP_WAIT1()  asm volatile("cp.async.wait_group 1;" ::: "memory")

// ---------------------------------------------------------------------------
// Kernel 1: h = gelu(z @ W0 + b0) -> g_h fp32 [b][k].  (proven FFMA version)
// ---------------------------------------------------------------------------
__global__ void __launch_bounds__(256) k1_gemm0(const float* __restrict__ z,
                                                const float* __restrict__ W0,
                                                const float* __restrict__ b0) {
    __shared__ float zs[4][DMEAN];
    const int tid = threadIdx.x;
    const int col = blockIdx.x * 64 + (tid & 63);
    const int bg  = blockIdx.y;
    const int brow = bg * 4 + (tid >> 6);

    for (int i = tid; i < 4 * DMEAN; i += 256) {
        int bb = i >> 10, kk = i & 1023;
        zs[bb][kk] = z[(bg * 4 + bb) * DMEAN + kk];
    }
    __syncthreads();

    const float* zr = zs[tid >> 6];
    const float* wp = W0 + col;
    float acc = 0.f;
#pragma unroll 32
    for (int k = 0; k < DMEAN; k++) {
        acc = fmaf(zr[k], wp[(size_t)k * DMV], acc);
    }
    float x = acc + b0[col];
    g_h[brow * DMV + col] = 0.5f * x * (1.f + erff(x * 0.70710678118654752f));
}

// ---------------------------------------------------------------------------
// Kernel 2: logits = h @ W1 + b1 + fused per-block LSE partials.
// TF32 mma, 256 thr, TM=256 (1KB W1 strips/k-row for DRAM row locality),
// KSTG=16, DEPTH-3 cp.async pipeline, 197 blocks. Warp w owns m-rows
// [w*32, w*32+32) as 2 m16 tiles. A via 16B cp.async from aligned-down row
// starts (VOCAB odd); fragment loads add (lane&3).
// ---------------------------------------------------------------------------
__global__ void __launch_bounds__(256, 2) k2_mma(const float* __restrict__ W1,
                                                 const float* __restrict__ b1) {
    extern __shared__ char sm[];
    const uint32_t smb = (uint32_t)__cvta_generic_to_shared(sm);
    const uint32_t bsb = smb + DEPTH * AW_STG * 4;
    const int t = threadIdx.x, w = t >> 5, lane = t & 31;
    const int vb = blockIdx.x * TM;

    auto fill = [&](int s, int buf) {
        const uint32_t Ab = smb + buf * AW_STG * 4;
        const uint32_t Bb = bsb + buf * BW_STG * 4;
        const int kr = s * KSTG;
        // A: 16 rows x 65 granules = 1040 16B copies
#pragma unroll
        for (int i = 0; i < 5; i++) {
            int idx = t + i * 256;
            if (idx < 1040) {
                int k = idx / 65, g = idx % 65;
                size_t g0 = (size_t)(kr + k) * VOCAB + vb;
                size_t gs = g0 - (size_t)(k & 3) + 4 * (size_t)g;
                if (gs > TOTW - 4) gs = TOTW - 4;
                cp_async16(Ab + (uint32_t)(k * AST + 4 * g) * 4, W1 + gs);
            }
        }
        // B: 32 rows x 4 granules = 128 copies
        if (t < 128) {
            int n = t >> 2, g = t & 3;
            cp_async16(Bb + (uint32_t)(n * BST + 4 * g) * 4,
                       g_h + (size_t)n * DMV + kr + 4 * g);
        }
    };

    fill(0, 0); CP_COMMIT();
    fill(1, 1); CP_COMMIT();

    float acc[2][4][4];
#pragma unroll
    for (int ms = 0; ms < 2; ms++)
#pragma unroll
        for (int j = 0; j < 4; j++)
#pragma unroll
            for (int q = 0; q < 4; q++) acc[ms][j][q] = 0.f;

    const int la = lane & 3;
    const int mq = lane >> 2;

    int buf = 0, pf = 2;
    for (int s = 0; s < NSTG; s++) {
        CP_WAIT1();
        __syncthreads();
        if (s + 2 < NSTG) fill(s + 2, pf);
        CP_COMMIT();

        const uint32_t Ab = smb + buf * AW_STG * 4;
        const uint32_t Bb = bsb + buf * BW_STG * 4;
#pragma unroll
        for (int ks = 0; ks < 2; ks++) {
            const int kb = ks * 8;
            uint32_t bf[4][2];
#pragma unroll
            for (int ns = 0; ns < 4; ns++) {
                int n = ns * 8 + mq;
                uint32_t r0 = Bb + (uint32_t)(n * BST + kb + la) * 4;
                bf[ns][0] = lds32(r0);
                bf[ns][1] = lds32(r0 + 4 * 4);
            }
#pragma unroll
            for (int ms = 0; ms < 2; ms++) {
                uint32_t a[4];
                int m = w * 32 + ms * 16 + mq;
                uint32_t r0 = Ab + (uint32_t)((kb + la) * AST + m + la) * 4;
                a[0] = lds32(r0);
                a[1] = lds32(r0 + 8 * 4);
                a[2] = lds32(r0 + 4 * AST * 4);
                a[3] = lds32(r0 + (4 * AST + 8) * 4);
#pragma unroll
                for (int ns = 0; ns < 4; ns++)
                    MMA1688(acc[ms][ns], a, bf[ns][0], bf[ns][1]);
            }
        }
        buf = (buf == DEPTH - 1) ? 0 : buf + 1;
        pf  = (pf  == DEPTH - 1) ? 0 : pf + 1;
    }

    // ---- epilogue: bias (in place), store logits, fused block LSE ----
#pragma unroll
    for (int ms = 0; ms < 2; ms++) {
        int v0 = vb + w * 32 + ms * 16 + mq;
        int v1 = v0 + 8;
        bool ok0 = v0 < VOCAB, ok1 = v1 < VOCAB;
        float bi0 = b1[min(v0, VOCAB - 1)];
        float bi1 = b1[min(v1, VOCAB - 1)];
#pragma unroll
        for (int ns = 0; ns < 4; ns++)
#pragma unroll
            for (int p = 0; p < 2; p++) {
                int b = ns * 8 + la * 2 + p;
                acc[ms][ns][p]     = ok0 ? acc[ms][ns][p] + bi0     : -INFINITY;
                acc[ms][ns][2 + p] = ok1 ? acc[ms][ns][2 + p] + bi1 : -INFINITY;
                if (ok0) g_logits[(size_t)b * VOCAB + v0] = acc[ms][ns][p];
                if (ok1) g_logits[(size_t)b * VOCAB + v1] = acc[ms][ns][2 + p];
            }
    }

    __syncthreads();                       // main-loop smem dead; alias it
    float* redm = reinterpret_cast<float*>(sm);        // [8][32]
    float* reds = redm + 8 * 32;                       // [8][32]

    float Mb[4][2];
#pragma unroll
    for (int ns = 0; ns < 4; ns++)
#pragma unroll
        for (int p = 0; p < 2; p++) {
            float m = fmaxf(fmaxf(acc[0][ns][p], acc[0][ns][2 + p]),
                            fmaxf(acc[1][ns][p], acc[1][ns][2 + p]));
            m = fmaxf(m, __shfl_xor_sync(0xffffffffu, m, 4));
            m = fmaxf(m, __shfl_xor_sync(0xffffffffu, m, 8));
            m = fmaxf(m, __shfl_xor_sync(0xffffffffu, m, 16));
            if (mq == 0) redm[w * 32 + ns * 8 + la * 2 + p] = m;
        }
    __syncthreads();

#pragma unroll
    for (int ns = 0; ns < 4; ns++)
#pragma unroll
        for (int p = 0; p < 2; p++) {
            int b = ns * 8 + la * 2 + p;
            float M = redm[b];
#pragma unroll
            for (int ww = 1; ww < 8; ww++) M = fmaxf(M, redm[ww * 32 + b]);
            Mb[ns][p] = M;
            float sx = expf(acc[0][ns][p] - M) + expf(acc[0][ns][2 + p] - M)
                     + expf(acc[1][ns][p] - M) + expf(acc[1][ns][2 + p] - M);
            sx += __shfl_xor_sync(0xffffffffu, sx, 4);
            sx += __shfl_xor_sync(0xffffffffu, sx, 8);
            sx += __shfl_xor_sync(0xffffffffu, sx, 16);
            if (mq == 0) reds[w * 32 + b] = sx;
        }
    __syncthreads();

    if (w == 0 && mq == 0) {
#pragma unroll
        for (int ns = 0; ns < 4; ns++)
#pragma unroll
            for (int p = 0; p < 2; p++) {
                int b = ns * 8 + la * 2 + p;
                float S = reds[b];
#pragma unroll
                for (int ww = 1; ww < 8; ww++) S += reds[ww * 32 + b];
                g_red[b][blockIdx.x][0] = Mb[ns][p];
                g_red[b][blockIdx.x][1] = S;
            }
    }
}

// ---------------------------------------------------------------------------
// Kernel 3: combine 197 per-block LSE partials + label gather + mean.
// ---------------------------------------------------------------------------
__global__ void __launch_bounds__(512) k3b_final(const int* __restrict__ labels,
                                                 float* __restrict__ out) {
    __shared__ float sM[BATCH][16], sS[BATCH][16], gsum[BATCH][16];
    __shared__ float rowpart[BATCH];
    const int tid = threadIdx.x;
    const int b = tid >> 4, c = tid & 15;

    float gacc = 0.f;
    const float* row = g_logits + (size_t)b * VOCAB;
#pragma unroll
    for (int i = 0; i < 8; i++) {
        int s = c + 16 * i;
        int lv = labels[b * SEQL + s];
        lv = max(0, min(lv, VOCAB - 1));
        gacc += row[lv];
    }
    gsum[b][c] = gacc;

    float M = -INFINITY;
    for (int i = c; i < NBV; i += 16) M = fmaxf(M, g_red[b][i][0]);
    sM[b][c] = M;
    __syncthreads();
    for (int s = 8; s > 0; s >>= 1) {
        if (c < s) {
            sM[b][c] = fmaxf(sM[b][c], sM[b][c + s]);
            gsum[b][c] += gsum[b][c + s];
        }
        __syncthreads();
    }
    const float Mrow = sM[b][0];
    __syncthreads();

    float S = 0.f;
    for (int i = c; i < NBV; i += 16)
        S += g_red[b][i][1] * expf(g_red[b][i][0] - Mrow);
    sS[b][c] = S;
    __syncthreads();
    for (int s = 8; s > 0; s >>= 1) {
        if (c < s) sS[b][c] += sS[b][c + s];
        __syncthreads();
    }
    if (c == 0)
        rowpart[b] = (float)SEQL * (Mrow + logf(sS[b][0])) - gsum[b][0];
    __syncthreads();
    if (tid == 0) {
        float s = 0.f;
        for (int i = 0; i < BATCH; i++) s += rowpart[i];
        out[0] = s / (float)(BATCH * SEQL);
    }
}

// ---------------------------------------------------------------------------
extern "C" void kernel_launch(void* const* d_in, const int* in_sizes, int n_in,
                              void* d_out, int out_size) {
    const float* z      = (const float*)d_in[0];
    const int*   labels = (const int*)d_in[1];
    const float* W0     = (const float*)d_in[2];
    const float* b0     = (const float*)d_in[3];
    const float* W1     = (const float*)d_in[4];
    const float* b1     = (const float*)d_in[5];
    float* out = (float*)d_out;

    cudaFuncSetAttribute(k2_mma, cudaFuncAttributeMaxDynamicSharedMemorySize,
                         K2_SMEM);

    k1_gemm0<<<dim3(16, 8), 256>>>(z, W0, b0);          // launch 1
    k2_mma<<<NBV, 256, K2_SMEM>>>(W1, b1);              // launch 2
    k3b_final<<<1, 512>>>(labels, out);                 // launch 3
}

// round 16
// speedup vs baseline: 1.6525x; 1.6525x over previous
#include <cuda_runtime.h>
#include <cuda_bf16.h>
#include <math.h>
#include <stdint.h>

#define VOCAB 50257
#define DMEAN 1024
#define DMV   1024
#define BATCH 32
#define SEQL  128
#define TOTW  ((size_t)DMV * VOCAB)       // W1 total words

// ---- k1 split-K config ----
#define K1_KS   16                        // k-splits (64 k each)
#define K1_JT   8                         // j-tiles (128 cols each)

// ---- k2 tf32 pipeline config (exact R12 best: 57.8us) ----
#define TM      128
#define KSTG    32
#define NSTG    (DMV / KSTG)              // 32
#define DEPTH   3
#define AST     136                       // 34 granules/k-row
#define BST     36                        // 36 % 32 == 4 -> conflict-free B frags
#define AW_STG  (KSTG * AST)              // 4352 words
#define BW_STG  (BATCH * BST)             // 1152 words
#define K2_SMEM ((DEPTH * (AW_STG + BW_STG)) * 4)   // 66048 B
#define NBV     ((VOCAB + TM - 1) / TM)   // 393

// ---- k3 split ----
#define NSL     8
#define SLW     6283                      // ceil(VOCAB/8)

// Scratch (device globals — no runtime allocation allowed)
__device__ float g_hp[K1_KS][BATCH][DMV]; // k1 split-K partials (2MB)
__device__ float g_h[BATCH * DMV];
__device__ float g_logits[BATCH * VOCAB];
__device__ float g_red[BATCH][NSL][2];    // per-slice {max, sumexp}

// ---------------------------------------------------------------------------
#define MMA1688(c, a, bb0, bb1)                                                \
    asm volatile("mma.sync.aligned.m16n8k8.row.col.f32.tf32.tf32.f32 "         \
                 "{%0,%1,%2,%3}, {%4,%5,%6,%7}, {%8,%9}, {%0,%1,%2,%3};"       \
                 : "+f"(c[0]), "+f"(c[1]), "+f"(c[2]), "+f"(c[3])              \
                 : "r"(a[0]), "r"(a[1]), "r"(a[2]), "r"(a[3]),                 \
                   "r"(bb0), "r"(bb1))

__device__ __forceinline__ void cp_async16(uint32_t dst, const void* src) {
    asm volatile("cp.async.cg.shared.global [%0], [%1], 16;"
                 :: "r"(dst), "l"(src) : "memory");
}
__device__ __forceinline__ uint32_t lds32(uint32_t a) {
    uint32_t v;
    asm volatile("ld.shared.b32 %0, [%1];" : "=r"(v) : "r"(a));
    return v;
}
#define CP_COMMIT() asm volatile("cp.async.commit_group;" ::: "memory")
#define CP_WAIT1()  asm volatile("cp.async.wait_group 1;" ::: "memory")

// ---------------------------------------------------------------------------
// kz: trivial init (keeps the profiled launch #4 = k2)
// ---------------------------------------------------------------------------
__global__ void kz_init() {
    if (threadIdx.x == 0) g_red[0][0][0] = 0.f;
}

// ---------------------------------------------------------------------------
// Kernel 1a: split-K partials of z @ W0.
// grid (K1_JT, K1_KS) = 128 blocks x 256 thr. Block (jt, ks): cols
// [jt*128, jt*128+128), k in [ks*64, ks*64+64). Thread: one col, 16 batch
// rows; 64 independent W0 loads per thread -> deep MLP, smem z broadcast.
// ---------------------------------------------------------------------------
__global__ void __launch_bounds__(256) k1a_part(const float* __restrict__ z,
                                                const float* __restrict__ W0) {
    __shared__ float zs[BATCH][64];
    const int t = threadIdx.x;
    const int jt = blockIdx.x, ks = blockIdx.y;
    const int k0 = ks * 64;

    // stage z[0:32][k0:k0+64] (512 float4, 2 per thread)
#pragma unroll
    for (int i = 0; i < 2; i++) {
        int idx = t + i * 256;
        int b = idx >> 4, q = idx & 15;
        float4 v = *reinterpret_cast<const float4*>(z + b * DMEAN + k0 + q * 4);
        zs[b][q * 4 + 0] = v.x;
        zs[b][q * 4 + 1] = v.y;
        zs[b][q * 4 + 2] = v.z;
        zs[b][q * 4 + 3] = v.w;
    }
    __syncthreads();

    const int col = jt * 128 + (t & 127);
    const int half = t >> 7;                // 0/1: batches [half*16, half*16+16)
    const float* wp = W0 + (size_t)k0 * DMV + col;

    float acc[16];
#pragma unroll
    for (int b = 0; b < 16; b++) acc[b] = 0.f;

#pragma unroll 8
    for (int kk = 0; kk < 64; kk++) {
        float wv = wp[kk * DMV];
#pragma unroll
        for (int b = 0; b < 16; b++)
            acc[b] = fmaf(zs[half * 16 + b][kk], wv, acc[b]);
    }

#pragma unroll
    for (int b = 0; b < 16; b++)
        g_hp[ks][half * 16 + b][col] = acc[b];
}

// ---------------------------------------------------------------------------
// Kernel 1b: reduce 16 partials + bias + exact GELU -> g_h fp32 [b][k].
// 128 blocks x 256 thr, one output each; partials are L2-resident.
// ---------------------------------------------------------------------------
__global__ void __launch_bounds__(256) k1b_reduce(const float* __restrict__ b0) {
    const int idx = blockIdx.x * 256 + threadIdx.x;   // 0..32767
    const int b = idx >> 10, col = idx & 1023;
    float s = 0.f;
#pragma unroll
    for (int ks = 0; ks < K1_KS; ks++) s += g_hp[ks][b][col];
    float x = s + b0[col];
    g_h[b * DMV + col] = 0.5f * x * (1.f + erff(x * 0.70710678118654752f));
}

// ---------------------------------------------------------------------------
// Kernel 2: logits = h @ W1 + b1.  EXACT R12 best config (57.8us).
// TF32 mma, 256 thr, DEPTH-3 pipeline, 393 blocks. A via 16B cp.async from
// aligned-down W1 row starts (VOCAB odd); fragment loads add (lane&3).
// ---------------------------------------------------------------------------
__global__ void __launch_bounds__(256, 3) k2_mma(const float* __restrict__ W1,
                                                 const float* __restrict__ b1) {
    extern __shared__ char sm[];
    const uint32_t smb = (uint32_t)__cvta_generic_to_shared(sm);
    const uint32_t bsb = smb + DEPTH * AW_STG * 4;
    const int t = threadIdx.x, w = t >> 5, lane = t & 31;
    const int vb = blockIdx.x * TM;

    auto fill = [&](int s, int buf) {
        const uint32_t Ab = smb + buf * AW_STG * 4;
        const uint32_t Bb = bsb + buf * BW_STG * 4;
        const int kr = s * KSTG;
        // A: 32 rows x 34 granules = 1088 16B copies
#pragma unroll
        for (int i = 0; i < 5; i++) {
            int idx = t + i * 256;
            if (idx < 1088) {
                int k = idx / 34, g = idx % 34;
                size_t g0 = (size_t)(kr + k) * VOCAB + vb;
                size_t gs = g0 - (size_t)(k & 3) + 4 * (size_t)g;
                if (gs > TOTW - 4) gs = TOTW - 4;
                cp_async16(Ab + (uint32_t)(k * AST + 4 * g) * 4, W1 + gs);
            }
        }
        // B: 256 16B copies (1/thread) from g_h (16B-aligned rows)
        {
            int n = t >> 3, g = t & 7;
            cp_async16(Bb + (uint32_t)(n * BST + 4 * g) * 4,
                       g_h + (size_t)n * DMV + kr + 4 * g);
        }
    };

    fill(0, 0); CP_COMMIT();
    fill(1, 1); CP_COMMIT();

    float acc[4][4];
#pragma unroll
    for (int j = 0; j < 4; j++)
#pragma unroll
        for (int q = 0; q < 4; q++) acc[j][q] = 0.f;

    const int la = lane & 3;
    const int mfrag = w * 16 + (lane >> 2);

    int buf = 0, pf = 2;
    for (int s = 0; s < NSTG; s++) {
        CP_WAIT1();
        __syncthreads();
        if (s + 2 < NSTG) fill(s + 2, pf);
        CP_COMMIT();

        const uint32_t Ab = smb + buf * AW_STG * 4;
        const uint32_t Bb = bsb + buf * BW_STG * 4;
#pragma unroll
        for (int ks = 0; ks < 4; ks++) {
            const int kb = ks * 8;
            uint32_t a[4], bf[4][2];
            {
                uint32_t r0 = Ab + (uint32_t)((kb + la) * AST + mfrag + la) * 4;
                a[0] = lds32(r0);
                a[1] = lds32(r0 + 8 * 4);
                a[2] = lds32(r0 + 4 * AST * 4);
                a[3] = lds32(r0 + (4 * AST + 8) * 4);
            }
#pragma unroll
            for (int ns = 0; ns < 4; ns++) {
                int n = ns * 8 + (lane >> 2);
                uint32_t r0 = Bb + (uint32_t)(n * BST + kb + la) * 4;
                bf[ns][0] = lds32(r0);
                bf[ns][1] = lds32(r0 + 4 * 4);
            }
#pragma unroll
            for (int ns = 0; ns < 4; ns++)
                MMA1688(acc[ns], a, bf[ns][0], bf[ns][1]);
        }
        buf = (buf == DEPTH - 1) ? 0 : buf + 1;
        pf  = (pf  == DEPTH - 1) ? 0 : pf + 1;
    }

    // epilogue
    {
        int v0 = vb + w * 16 + (lane >> 2);
        int v1 = v0 + 8;
        float bi0 = b1[min(v0, VOCAB - 1)];
        float bi1 = b1[min(v1, VOCAB - 1)];
#pragma unroll
        for (int ns = 0; ns < 4; ns++) {
            int b = ns * 8 + (lane & 3) * 2;
            if (v0 < VOCAB) {
                g_logits[(size_t)b * VOCAB + v0]       = acc[ns][0] + bi0;
                g_logits[(size_t)(b + 1) * VOCAB + v0] = acc[ns][1] + bi0;
            }
            if (v1 < VOCAB) {
                g_logits[(size_t)b * VOCAB + v1]       = acc[ns][2] + bi1;
                g_logits[(size_t)(b + 1) * VOCAB + v1] = acc[ns][3] + bi1;
            }
        }
    }
}

// ---------------------------------------------------------------------------
// Kernel 3a: per (row, slice) max + sumexp.  grid (NSL, BATCH) = 256 blocks.
// ---------------------------------------------------------------------------
__global__ void __launch_bounds__(256) k3a_slice() {
    const int b = blockIdx.y, sl = blockIdx.x;
    const int tid = threadIdx.x;
    const int v0 = sl * SLW, v1 = min(v0 + SLW, VOCAB);
    const float* row = g_logits + (size_t)b * VOCAB;
    __shared__ float red[256];

    float m = -INFINITY;
    for (int v = v0 + tid; v < v1; v += 256) m = fmaxf(m, row[v]);
    red[tid] = m; __syncthreads();
    for (int s = 128; s > 0; s >>= 1) {
        if (tid < s) red[tid] = fmaxf(red[tid], red[tid + s]);
        __syncthreads();
    }
    const float M = red[0]; __syncthreads();

    float ssum = 0.f;
    for (int v = v0 + tid; v < v1; v += 256) ssum += expf(row[v] - M);
    red[tid] = ssum; __syncthreads();
    for (int s = 128; s > 0; s >>= 1) {
        if (tid < s) red[tid] += red[tid + s];
        __syncthreads();
    }
    if (tid == 0) { g_red[b][sl][0] = M; g_red[b][sl][1] = red[0]; }
}

// ---------------------------------------------------------------------------
// Kernel 3b: combine slices + label gather + final mean.  1 block, 512 thr.
// ---------------------------------------------------------------------------
__global__ void __launch_bounds__(512) k3b_final(const int* __restrict__ labels,
                                                 float* __restrict__ out) {
    __shared__ float gsum[BATCH][16];
    __shared__ float rowpart[BATCH];
    const int tid = threadIdx.x;
    const int b = tid >> 4, sl16 = tid & 15;

    float gacc = 0.f;
    const float* row = g_logits + (size_t)b * VOCAB;
#pragma unroll
    for (int i = 0; i < 8; i++) {
        int s = sl16 + 16 * i;
        int lv = labels[b * SEQL + s];
        lv = max(0, min(lv, VOCAB - 1));
        gacc += row[lv];
    }
    gsum[b][sl16] = gacc;
    __syncthreads();
    for (int s = 8; s > 0; s >>= 1) {
        if (sl16 < s) gsum[b][sl16] += gsum[b][sl16 + s];
        __syncthreads();
    }

    if (tid < BATCH) {
        float M = -INFINITY;
#pragma unroll
        for (int i = 0; i < NSL; i++) M = fmaxf(M, g_red[tid][i][0]);
        float S = 0.f;
#pragma unroll
        for (int i = 0; i < NSL; i++)
            S += g_red[tid][i][1] * expf(g_red[tid][i][0] - M);
        rowpart[tid] = (float)SEQL * (M + logf(S)) - gsum[tid][0];
    }
    __syncthreads();
    if (tid == 0) {
        float s = 0.f;
        for (int i = 0; i < BATCH; i++) s += rowpart[i];
        out[0] = s / (float)(BATCH * SEQL);
    }
}

// ---------------------------------------------------------------------------
extern "C" void kernel_launch(void* const* d_in, const int* in_sizes, int n_in,
                              void* d_out, int out_size) {
    const float* z      = (const float*)d_in[0];
    const int*   labels = (const int*)d_in[1];
    const float* W0     = (const float*)d_in[2];
    const float* b0     = (const float*)d_in[3];
    const float* W1     = (const float*)d_in[4];
    const float* b1     = (const float*)d_in[5];
    float* out = (float*)d_out;

    cudaFuncSetAttribute(k2_mma, cudaFuncAttributeMaxDynamicSharedMemorySize,
                         K2_SMEM);

    kz_init<<<1, 32>>>();                                 // launch 1
    k1a_part<<<dim3(K1_JT, K1_KS), 256>>>(z, W0);         // launch 2
    k1b_reduce<<<128, 256>>>(b0);                         // launch 3
    k2_mma<<<NBV, 256, K2_SMEM>>>(W1, b1);                // launch 4 <- profiled
    k3a_slice<<<dim3(NSL, BATCH), 256>>>();               // launch 5
    k3b_final<<<1, 512>>>(labels, out);                   // launch 6
}